// round 3
// baseline (speedup 1.0000x reference)
#include <cuda_runtime.h>
#include <math.h>

#define BATCH 128
#define TSTEPS 512
#define DDIM 1024
#define HDIM 1024

// per-rowgroup, per-step arrival counters (4 rowgroups x 512 steps)
__device__ int g_cnt[4 * TSTEPS];

__global__ void reset_kernel() {
    int i = blockIdx.x * blockDim.x + threadIdx.x;
    if (i < 4 * TSTEPS) g_cnt[i] = 0;
}

// ---------------------------------------------------------------------------
// Phase 1: C[M,H] = A[M,D] @ W[D,H] + bias, M = BATCH*TSTEPS = 65536
// 64x64 tile, BK=16, 256 threads, 4x4 per thread.
// ---------------------------------------------------------------------------
__global__ void __launch_bounds__(256) gemm_xw_kernel(
    const float* __restrict__ A, const float* __restrict__ W,
    const float* __restrict__ bias, float* __restrict__ C)
{
    __shared__ float sA[16][68];   // [k][m]
    __shared__ float sB[16][68];   // [k][n]

    const int tid = threadIdx.x;
    const int n0 = blockIdx.x * 64;
    const int m0 = blockIdx.y * 64;
    const int ty = tid >> 4;        // 0..15 -> rows ty*4..+3
    const int tx = tid & 15;        // 0..15 -> cols tx*4..+3

    const int ar = tid >> 2;        // 0..63 (row of A tile)
    const int ak = (tid & 3) << 2;  // 0,4,8,12
    const int bk = tid >> 4;        // 0..15 (row of B tile)
    const int bn = (tid & 15) << 2; // 0..60

    float acc[4][4] = {};

    const float* Arow = A + (size_t)(m0 + ar) * DDIM + ak;
    const float* Wrow = W + (size_t)bk * HDIM + n0 + bn;

    for (int k0 = 0; k0 < DDIM; k0 += 16) {
        float4 av = *(const float4*)(Arow + k0);
        float4 bv = *(const float4*)(Wrow + (size_t)k0 * HDIM);
        sA[ak + 0][ar] = av.x;
        sA[ak + 1][ar] = av.y;
        sA[ak + 2][ar] = av.z;
        sA[ak + 3][ar] = av.w;
        *(float4*)&sB[bk][bn] = bv;
        __syncthreads();
        #pragma unroll
        for (int kk = 0; kk < 16; ++kk) {
            float4 a = *(const float4*)&sA[kk][ty * 4];
            float4 b = *(const float4*)&sB[kk][tx * 4];
            float ax[4] = {a.x, a.y, a.z, a.w};
            float bx[4] = {b.x, b.y, b.z, b.w};
            #pragma unroll
            for (int i = 0; i < 4; ++i)
                #pragma unroll
                for (int j = 0; j < 4; ++j)
                    acc[i][j] += ax[i] * bx[j];
        }
        __syncthreads();
    }

    float4 bb = *(const float4*)&bias[n0 + tx * 4];
    #pragma unroll
    for (int i = 0; i < 4; ++i) {
        float4 o;
        o.x = acc[i][0] + bb.x;
        o.y = acc[i][1] + bb.y;
        o.z = acc[i][2] + bb.z;
        o.w = acc[i][3] + bb.w;
        *(float4*)&C[(size_t)(m0 + ty * 4 + i) * HDIM + n0 + tx * 4] = o;
    }
}

// ---------------------------------------------------------------------------
// Phase 2: persistent scan. Grid (32 colgroups, 4 rowgroups), 256 threads.
// Each CTA owns a 32-row x 32-col output tile for ALL 512 steps.
// Wh slice [1024][32] lives in smem for the whole kernel (loaded once).
// h chunk [256][32] (transposed) is staged per k-chunk each step.
// Inter-step sync: per-rowgroup monotone counter barrier (32 arrivals).
// ---------------------------------------------------------------------------
#define WH_STRIDE 36   // float4-store + float2-load aligned, conflict-free loads
#define SH_STRIDE 34   // float2-load aligned
#define SCAN_SMEM_BYTES ((DDIM * WH_STRIDE + 256 * SH_STRIDE) * 4)

__global__ void __launch_bounds__(256) scan_kernel(
    const float* __restrict__ h0, const float* __restrict__ Wh,
    float* __restrict__ out)
{
    extern __shared__ float smem[];
    float* sWh = smem;                    // [1024][WH_STRIDE]
    float* sh  = smem + DDIM * WH_STRIDE; // [256][SH_STRIDE]

    const int tid = threadIdx.x;
    const int cg = blockIdx.x;   // 0..31 column group
    const int rg = blockIdx.y;   // 0..3  row group
    const int ty = tid >> 4;     // 0..15 -> rows 2*ty..+1
    const int tx = tid & 15;     // 0..15 -> cols 2*tx..+1

    // --- load Wh slice once: cols [cg*32, cg*32+32) ---
    {
        const int kb = tid >> 3;          // 0..31
        const int j4 = (tid & 7) * 4;     // 0..28
        #pragma unroll 4
        for (int it = 0; it < 32; ++it) {
            int k = kb + it * 32;
            float4 w = *(const float4*)&Wh[(size_t)k * HDIM + cg * 32 + j4];
            *(float4*)&sWh[k * WH_STRIDE + j4] = w;
        }
    }
    __syncthreads();

    const int r = tid >> 3;      // 0..31 local row for h staging
    const int x = tid & 7;       // 8 threads per row
    const int row = rg * 32 + r; // global batch row this thread stages

    int* cnt = &g_cnt[rg * TSTEPS];

    for (int t = 0; t < TSTEPS; ++t) {
        float acc00 = 0.f, acc01 = 0.f, acc10 = 0.f, acc11 = 0.f;
        const float* hrow = (t == 0)
            ? (h0 + (size_t)row * HDIM)
            : (out + ((size_t)row * TSTEPS + (t - 1)) * HDIM);

        #pragma unroll 1
        for (int kc = 0; kc < 4; ++kc) {
            // stage h chunk transposed: sh[lk][r]
            #pragma unroll
            for (int q = 0; q < 8; ++q) {
                int lk = x * 4 + q * 32;
                float4 v = *(const float4*)&hrow[kc * 256 + lk];
                sh[(lk + 0) * SH_STRIDE + r] = v.x;
                sh[(lk + 1) * SH_STRIDE + r] = v.y;
                sh[(lk + 2) * SH_STRIDE + r] = v.z;
                sh[(lk + 3) * SH_STRIDE + r] = v.w;
            }
            __syncthreads();

            const float* hbase = sh + ty * 2;
            const float* wbase = sWh + (size_t)(kc * 256) * WH_STRIDE + tx * 2;
            #pragma unroll 8
            for (int lk = 0; lk < 256; ++lk) {
                float2 a = *(const float2*)(hbase + lk * SH_STRIDE);
                float2 w = *(const float2*)(wbase + lk * WH_STRIDE);
                acc00 += a.x * w.x;
                acc01 += a.x * w.y;
                acc10 += a.y * w.x;
                acc11 += a.y * w.y;
            }
            __syncthreads();
        }

        // epilogue: h = tanh(acc + xw) written in place over xw
        {
            int m0 = rg * 32 + ty * 2;
            int n  = cg * 32 + tx * 2;
            float* p0 = out + ((size_t)m0 * TSTEPS + t) * HDIM + n;
            float* p1 = out + ((size_t)(m0 + 1) * TSTEPS + t) * HDIM + n;
            float2 xw0 = *(const float2*)p0;
            float2 xw1 = *(const float2*)p1;
            float2 o0, o1;
            o0.x = tanhf(acc00 + xw0.x);
            o0.y = tanhf(acc01 + xw0.y);
            o1.x = tanhf(acc10 + xw1.x);
            o1.y = tanhf(acc11 + xw1.y);
            *(float2*)p0 = o0;
            *(float2*)p1 = o1;
        }

        // inter-step barrier among the 32 CTAs of this rowgroup
        if (t < TSTEPS - 1) {
            __threadfence();     // make this thread's h stores GPU-visible
            __syncthreads();     // all threads of CTA fenced
            if (tid == 0) {
                atomicAdd(cnt + t, 1);
                while (((volatile int*)cnt)[t] < 32) { }
                __threadfence(); // acquire
            }
            __syncthreads();
        }
    }
}

extern "C" void kernel_launch(void* const* d_in, const int* in_sizes, int n_in,
                              void* d_out, int out_size) {
    const float* x  = (const float*)d_in[0];  // (128, 512, 1024)
    const float* h0 = (const float*)d_in[1];  // (128, 1024)
    const float* Wx = (const float*)d_in[2];  // (1024, 1024)
    const float* Wh = (const float*)d_in[3];  // (1024, 1024)
    const float* b  = (const float*)d_in[4];  // (1024,)
    float* out = (float*)d_out;               // (128, 512, 1024)

    // Phase 1: out = x @ Wx + b   (M = 65536, N = 1024, K = 1024)
    {
        dim3 grid(HDIM / 64, (BATCH * TSTEPS) / 64);
        gemm_xw_kernel<<<grid, 256>>>(x, Wx, b, out);
    }

    // reset barrier counters (deterministic across graph replays)
    reset_kernel<<<4, 512>>>();

    // Phase 2: persistent scan
    {
        static int smem_set = 0;
        if (!smem_set) {
            cudaFuncSetAttribute(scan_kernel,
                                 cudaFuncAttributeMaxDynamicSharedMemorySize,
                                 SCAN_SMEM_BYTES);
            smem_set = 1;
        }
        dim3 grid(32, 4);
        scan_kernel<<<grid, 256, SCAN_SMEM_BYTES>>>(h0, Wh, out);
    }
}

// round 4
// speedup vs baseline: 1.6081x; 1.6081x over previous
#include <cuda_runtime.h>
#include <math.h>

#define BATCH 128
#define TSTEPS 512
#define DDIM 1024
#define HDIM 1024

// per-rowgroup, per-step arrival counters (4 rowgroups x 512 steps)
__device__ int g_cnt[4 * TSTEPS];

__global__ void reset_kernel() {
    int i = blockIdx.x * blockDim.x + threadIdx.x;
    if (i < 4 * TSTEPS) g_cnt[i] = 0;
}

// ---------------------------------------------------------------------------
// Phase 1: C[M,H] = A[M,D] @ W[D,H] + bias, M = BATCH*TSTEPS = 65536
// 64x64 tile, BK=16, 256 threads, 4x4 per thread.
// ---------------------------------------------------------------------------
__global__ void __launch_bounds__(256) gemm_xw_kernel(
    const float* __restrict__ A, const float* __restrict__ W,
    const float* __restrict__ bias, float* __restrict__ C)
{
    __shared__ float sA[16][68];   // [k][m]
    __shared__ float sB[16][68];   // [k][n]

    const int tid = threadIdx.x;
    const int n0 = blockIdx.x * 64;
    const int m0 = blockIdx.y * 64;
    const int ty = tid >> 4;        // 0..15 -> rows ty*4..+3
    const int tx = tid & 15;        // 0..15 -> cols tx*4..+3

    const int ar = tid >> 2;        // 0..63 (row of A tile)
    const int ak = (tid & 3) << 2;  // 0,4,8,12
    const int bk = tid >> 4;        // 0..15 (row of B tile)
    const int bn = (tid & 15) << 2; // 0..60

    float acc[4][4] = {};

    const float* Arow = A + (size_t)(m0 + ar) * DDIM + ak;
    const float* Wrow = W + (size_t)bk * HDIM + n0 + bn;

    for (int k0 = 0; k0 < DDIM; k0 += 16) {
        float4 av = *(const float4*)(Arow + k0);
        float4 bv = *(const float4*)(Wrow + (size_t)k0 * HDIM);
        sA[ak + 0][ar] = av.x;
        sA[ak + 1][ar] = av.y;
        sA[ak + 2][ar] = av.z;
        sA[ak + 3][ar] = av.w;
        *(float4*)&sB[bk][bn] = bv;
        __syncthreads();
        #pragma unroll
        for (int kk = 0; kk < 16; ++kk) {
            float4 a = *(const float4*)&sA[kk][ty * 4];
            float4 b = *(const float4*)&sB[kk][tx * 4];
            float ax[4] = {a.x, a.y, a.z, a.w};
            float bx[4] = {b.x, b.y, b.z, b.w};
            #pragma unroll
            for (int i = 0; i < 4; ++i)
                #pragma unroll
                for (int j = 0; j < 4; ++j)
                    acc[i][j] += ax[i] * bx[j];
        }
        __syncthreads();
    }

    float4 bb = *(const float4*)&bias[n0 + tx * 4];
    #pragma unroll
    for (int i = 0; i < 4; ++i) {
        float4 o;
        o.x = acc[i][0] + bb.x;
        o.y = acc[i][1] + bb.y;
        o.z = acc[i][2] + bb.z;
        o.w = acc[i][3] + bb.w;
        *(float4*)&C[(size_t)(m0 + ty * 4 + i) * HDIM + n0 + tx * 4] = o;
    }
}

// ---------------------------------------------------------------------------
// Phase 2: persistent scan. Grid (32 colgroups, 4 rowgroups), 256 threads.
// Each CTA owns a 32-row x 32-col output tile for ALL 512 steps.
// Wh slice [1024][32] lives in smem for the whole kernel (loaded once).
// h chunk [256][32] (transposed) is staged per k-chunk each step.
// Inter-step sync: per-rowgroup monotone counter barrier (32 arrivals).
// ---------------------------------------------------------------------------
#define WH_STRIDE 36   // float4-store + float2-load aligned, conflict-free loads
#define SH_STRIDE 34   // float2-load aligned
#define SCAN_SMEM_BYTES ((DDIM * WH_STRIDE + 256 * SH_STRIDE) * 4)

__global__ void __launch_bounds__(256) scan_kernel(
    const float* __restrict__ h0, const float* __restrict__ Wh,
    float* __restrict__ out)
{
    extern __shared__ float smem[];
    float* sWh = smem;                    // [1024][WH_STRIDE]
    float* sh  = smem + DDIM * WH_STRIDE; // [256][SH_STRIDE]

    const int tid = threadIdx.x;
    const int cg = blockIdx.x;   // 0..31 column group
    const int rg = blockIdx.y;   // 0..3  row group
    const int ty = tid >> 4;     // 0..15 -> rows 2*ty..+1
    const int tx = tid & 15;     // 0..15 -> cols 2*tx..+1

    // --- load Wh slice once: cols [cg*32, cg*32+32) ---
    {
        const int kb = tid >> 3;          // 0..31
        const int j4 = (tid & 7) * 4;     // 0..28
        #pragma unroll 4
        for (int it = 0; it < 32; ++it) {
            int k = kb + it * 32;
            float4 w = *(const float4*)&Wh[(size_t)k * HDIM + cg * 32 + j4];
            *(float4*)&sWh[k * WH_STRIDE + j4] = w;
        }
    }
    __syncthreads();

    const int r = tid >> 3;      // 0..31 local row for h staging
    const int x = tid & 7;       // 8 threads per row
    const int row = rg * 32 + r; // global batch row this thread stages

    int* cnt = &g_cnt[rg * TSTEPS];

    for (int t = 0; t < TSTEPS; ++t) {
        float acc00 = 0.f, acc01 = 0.f, acc10 = 0.f, acc11 = 0.f;
        const float* hrow = (t == 0)
            ? (h0 + (size_t)row * HDIM)
            : (out + ((size_t)row * TSTEPS + (t - 1)) * HDIM);

        #pragma unroll 1
        for (int kc = 0; kc < 4; ++kc) {
            // stage h chunk transposed: sh[lk][r]
            #pragma unroll
            for (int q = 0; q < 8; ++q) {
                int lk = x * 4 + q * 32;
                float4 v = *(const float4*)&hrow[kc * 256 + lk];
                sh[(lk + 0) * SH_STRIDE + r] = v.x;
                sh[(lk + 1) * SH_STRIDE + r] = v.y;
                sh[(lk + 2) * SH_STRIDE + r] = v.z;
                sh[(lk + 3) * SH_STRIDE + r] = v.w;
            }
            __syncthreads();

            const float* hbase = sh + ty * 2;
            const float* wbase = sWh + (size_t)(kc * 256) * WH_STRIDE + tx * 2;
            #pragma unroll 8
            for (int lk = 0; lk < 256; ++lk) {
                float2 a = *(const float2*)(hbase + lk * SH_STRIDE);
                float2 w = *(const float2*)(wbase + lk * WH_STRIDE);
                acc00 += a.x * w.x;
                acc01 += a.x * w.y;
                acc10 += a.y * w.x;
                acc11 += a.y * w.y;
            }
            __syncthreads();
        }

        // epilogue: h = tanh(acc + xw) written in place over xw
        {
            int m0 = rg * 32 + ty * 2;
            int n  = cg * 32 + tx * 2;
            float* p0 = out + ((size_t)m0 * TSTEPS + t) * HDIM + n;
            float* p1 = out + ((size_t)(m0 + 1) * TSTEPS + t) * HDIM + n;
            float2 xw0 = *(const float2*)p0;
            float2 xw1 = *(const float2*)p1;
            float2 o0, o1;
            o0.x = tanhf(acc00 + xw0.x);
            o0.y = tanhf(acc01 + xw0.y);
            o1.x = tanhf(acc10 + xw1.x);
            o1.y = tanhf(acc11 + xw1.y);
            *(float2*)p0 = o0;
            *(float2*)p1 = o1;
        }

        // inter-step barrier among the 32 CTAs of this rowgroup
        if (t < TSTEPS - 1) {
            __threadfence();     // make this thread's h stores GPU-visible
            __syncthreads();     // all threads of CTA fenced
            if (tid == 0) {
                atomicAdd(cnt + t, 1);
                while (((volatile int*)cnt)[t] < 32) { }
                __threadfence(); // acquire
            }
            __syncthreads();
        }
    }
}

extern "C" void kernel_launch(void* const* d_in, const int* in_sizes, int n_in,
                              void* d_out, int out_size) {
    const float* x  = (const float*)d_in[0];  // (128, 512, 1024)
    const float* h0 = (const float*)d_in[1];  // (128, 1024)
    const float* Wx = (const float*)d_in[2];  // (1024, 1024)
    const float* Wh = (const float*)d_in[3];  // (1024, 1024)
    const float* b  = (const float*)d_in[4];  // (1024,)
    float* out = (float*)d_out;               // (128, 512, 1024)

    // Phase 1: out = x @ Wx + b   (M = 65536, N = 1024, K = 1024)
    {
        dim3 grid(HDIM / 64, (BATCH * TSTEPS) / 64);
        gemm_xw_kernel<<<grid, 256>>>(x, Wx, b, out);
    }

    // reset barrier counters (deterministic across graph replays)
    reset_kernel<<<4, 512>>>();

    // Phase 2: persistent scan
    {
        static int smem_set = 0;
        if (!smem_set) {
            cudaFuncSetAttribute(scan_kernel,
                                 cudaFuncAttributeMaxDynamicSharedMemorySize,
                                 SCAN_SMEM_BYTES);
            smem_set = 1;
        }
        dim3 grid(32, 4);
        scan_kernel<<<grid, 256, SCAN_SMEM_BYTES>>>(h0, Wh, out);
    }
}